// round 3
// baseline (speedup 1.0000x reference)
#include <cuda_runtime.h>
#include <cstdint>

#define BATCH 16
#define NPTS  4096
#define CH    64
#define MCENT 1024
#define KNB   32
#define RAD2  0.04f

// scratch (allocation-free rule: __device__ globals)
__device__ float g_pf[BATCH * NPTS * 64];        // 16 MB: W1[:,3:]@feat + b1, [b][n][64]
__device__ int   g_nidx[BATCH * MCENT * KNB];    // 2 MB

// ---------------------------------------------------------------------------
// Kernel 1: farthest point sampling. 1 block per batch, 512 threads, 8 pts/thr.
// Writes centroids straight into d_out[0 .. B*3*M) in [b][3][m] layout.
// ---------------------------------------------------------------------------
__global__ void __launch_bounds__(512) fps_kernel(const float* __restrict__ pts,
                                                  float* __restrict__ cent_out) {
    extern __shared__ float fs[];
    float* spx = fs;
    float* spy = fs + NPTS;
    float* spz = fs + 2 * NPTS;
    float* sc  = fs + 3 * NPTS;                          // 3 floats (+1 pad)
    unsigned long long* sKey = (unsigned long long*)(fs + 3 * NPTS + 4);

    const int b   = blockIdx.x;
    const int tid = threadIdx.x;
    const float* pb = pts + b * 3 * NPTS;

    float px[8], py[8], pz[8], dist[8];
#pragma unroll
    for (int i = 0; i < 8; i++) {
        int n = tid + i * 512;
        px[i] = pb[n]; py[i] = pb[NPTS + n]; pz[i] = pb[2 * NPTS + n];
        spx[n] = px[i]; spy[n] = py[i]; spz[n] = pz[i];
        dist[i] = 1e10f;
    }
    float* centb = cent_out + b * 3 * MCENT;
    if (tid == 0) {
        sc[0] = spx[0]; sc[1] = spy[0]; sc[2] = spz[0];
        centb[0] = spx[0]; centb[MCENT] = spy[0]; centb[2 * MCENT] = spz[0];
    }
    __syncthreads();

    for (int m = 1; m < MCENT; m++) {
        const float cx = sc[0], cy = sc[1], cz = sc[2];
        unsigned long long best = 0ull;
#pragma unroll
        for (int i = 0; i < 8; i++) {
            float dx = px[i] - cx, dy = py[i] - cy, dz = pz[i] - cz;
            float d  = dx * dx + dy * dy + dz * dz;
            float nd = fminf(dist[i], d);
            dist[i] = nd;
            unsigned long long key =
                ((unsigned long long)__float_as_uint(nd) << 32) |
                (unsigned)(NPTS - 1 - (tid + i * 512));
            if (key > best) best = key;
        }
#pragma unroll
        for (int off = 16; off; off >>= 1) {
            unsigned long long o = __shfl_down_sync(0xffffffffu, best, off);
            if (o > best) best = o;
        }
        if ((tid & 31) == 0) sKey[tid >> 5] = best;
        __syncthreads();
        if (tid < 32) {
            unsigned long long k = (tid < 16) ? sKey[tid] : 0ull;
#pragma unroll
            for (int off = 8; off; off >>= 1) {
                unsigned long long o = __shfl_down_sync(0xffffffffu, k, off);
                if (o > k) k = o;
            }
            if (tid == 0) {
                int n = NPTS - 1 - (int)(k & 0xffffffffu);
                float nx = spx[n], ny = spy[n], nz = spz[n];
                sc[0] = nx; sc[1] = ny; sc[2] = nz;
                centb[m] = nx; centb[MCENT + m] = ny; centb[2 * MCENT + m] = nz;
            }
        }
        __syncthreads();
    }
}

// ---------------------------------------------------------------------------
// Kernel 2: ball query. One warp per centroid; ordered ballot scan over N,
// taking the first K (by index) points with d2 <= R^2, padded with first hit.
// d2 computed in the reference's algebraic form (c2 + p2 - 2*dot).
// ---------------------------------------------------------------------------
__global__ void __launch_bounds__(256) ballq_kernel(const float* __restrict__ pts,
                                                    const float* __restrict__ cent) {
    int gwarp = (blockIdx.x * blockDim.x + threadIdx.x) >> 5;
    int lane  = threadIdx.x & 31;
    if (gwarp >= BATCH * MCENT) return;
    int b = gwarp >> 10, m = gwarp & 1023;
    const float* pb = pts + b * 3 * NPTS;
    const float* cb = cent + b * 3 * MCENT;
    float cx = cb[m], cy = cb[MCENT + m], cz = cb[2 * MCENT + m];
    float c2 = cx * cx + cy * cy + cz * cz;
    int* ni = g_nidx + (b * MCENT + m) * KNB;

    int cnt = 0, first = -1;
    for (int base = 0; base < NPTS; base += 32) {
        int n = base + lane;
        float x = pb[n], y = pb[NPTS + n], z = pb[2 * NPTS + n];
        float p2  = x * x + y * y + z * z;
        float dot = cx * x + cy * y + cz * z;
        float d2  = c2 + p2 - 2.f * dot;
        bool hit = (d2 <= RAD2);
        unsigned mask = __ballot_sync(0xffffffffu, hit);
        if (mask) {
            if (first < 0) first = base + __ffs(mask) - 1;
            if (hit) {
                int rank = cnt + __popc(mask & ((1u << lane) - 1u));
                if (rank < KNB) ni[rank] = n;
            }
            cnt += __popc(mask);
            if (cnt >= KNB) break;
        }
    }
    if (cnt < KNB) {
        int f = (first < 0) ? (NPTS - 1) : first;
        for (int s = cnt + lane; s < KNB; s += 32) ni[s] = f;
    }
}

// ---------------------------------------------------------------------------
// Kernel 3: precompute pf[b][n][o] = b1[o] + sum_c w1[o][3+c] * feats[b][c][n]
// ---------------------------------------------------------------------------
__global__ void __launch_bounds__(128) pf_kernel(const float* __restrict__ feats,
                                                 const float* __restrict__ w1,
                                                 const float* __restrict__ b1) {
    __shared__ float w1s[64][64];   // [c][o]
    __shared__ float b1s[64];
    int tid = threadIdx.x;
    for (int i = tid; i < 64 * 64; i += 128) {
        int c = i >> 6, o = i & 63;
        w1s[c][o] = w1[o * 67 + 3 + c];
    }
    if (tid < 64) b1s[tid] = b1[tid];
    __syncthreads();

    int b = blockIdx.y;
    int n = blockIdx.x * 128 + tid;
    const float* fb = feats + b * CH * NPTS + n;

    float acc[64];
#pragma unroll
    for (int o = 0; o < 64; o++) acc[o] = b1s[o];
#pragma unroll 4
    for (int c = 0; c < 64; c++) {
        float f = fb[c * NPTS];
#pragma unroll
        for (int o = 0; o < 64; o += 4) {
            float4 w = *(const float4*)&w1s[c][o];
            acc[o]     = fmaf(w.x, f, acc[o]);
            acc[o + 1] = fmaf(w.y, f, acc[o + 1]);
            acc[o + 2] = fmaf(w.z, f, acc[o + 2]);
            acc[o + 3] = fmaf(w.w, f, acc[o + 3]);
        }
    }
    float* dst = g_pf + (b * NPTS + n) * 64;
#pragma unroll
    for (int o = 0; o < 64; o += 4)
        *(float4*)(dst + o) = make_float4(acc[o], acc[o + 1], acc[o + 2], acc[o + 3]);
}

// ---------------------------------------------------------------------------
// Kernel 4: fused gather + 3-layer MLP + maxpool. Block = 4 groups (128 rows),
// 128 threads, 8x8 register tiles through padded smem (stride 68 = 16B mult).
// ---------------------------------------------------------------------------
template <int WS>
__device__ __forceinline__ void gemm8x8(const float* __restrict__ A,
                                        const float* __restrict__ W,
                                        int r0, int o0, float (&acc)[8][8]) {
#pragma unroll
    for (int i = 0; i < 8; i++)
#pragma unroll
        for (int j = 0; j < 8; j++) acc[i][j] = 0.f;

#pragma unroll 2
    for (int cc = 0; cc < 64; cc += 4) {
        float4 a[8];
#pragma unroll
        for (int i = 0; i < 8; i++) a[i] = *(const float4*)(A + (r0 + i) * 68 + cc);
#pragma unroll
        for (int j = 0; j < 4; j++) {
            float4 blo = *(const float4*)(W + (cc + j) * WS + o0);
            float4 bhi = *(const float4*)(W + (cc + j) * WS + o0 + 4);
#pragma unroll
            for (int i = 0; i < 8; i++) {
                float av = (j == 0) ? a[i].x : (j == 1) ? a[i].y : (j == 2) ? a[i].z : a[i].w;
                acc[i][0] = fmaf(av, blo.x, acc[i][0]);
                acc[i][1] = fmaf(av, blo.y, acc[i][1]);
                acc[i][2] = fmaf(av, blo.z, acc[i][2]);
                acc[i][3] = fmaf(av, blo.w, acc[i][3]);
                acc[i][4] = fmaf(av, bhi.x, acc[i][4]);
                acc[i][5] = fmaf(av, bhi.y, acc[i][5]);
                acc[i][6] = fmaf(av, bhi.z, acc[i][6]);
                acc[i][7] = fmaf(av, bhi.w, acc[i][7]);
            }
        }
    }
}

__global__ void __launch_bounds__(128) mlp_kernel(
    const float* __restrict__ pts,
    const float* __restrict__ w1, const float* __restrict__ g1, const float* __restrict__ be1,
    const float* __restrict__ w2, const float* __restrict__ b2,
    const float* __restrict__ g2, const float* __restrict__ be2,
    const float* __restrict__ w3, const float* __restrict__ b3,
    const float* __restrict__ g3, const float* __restrict__ be3,
    const float* __restrict__ cent, float* __restrict__ out) {
    extern __shared__ float sm[];
    float* bufA  = sm;                      // 128*68
    float* bufB  = bufA + 128 * 68;         // 128*68
    float* w2s   = bufB + 128 * 68;         // [c][o] 64*64
    float* w3s   = w2s + 64 * 64;           // [c][o] 64*128
    float* w1ps  = w3s + 64 * 128;          // [d][o] 3*64
    float* s1    = w1ps + 192;
    float* be1s  = s1 + 64;
    float* b2s   = be1s + 64;
    float* s2    = b2s + 64;
    float* be2s  = s2 + 64;
    float* b3s   = be2s + 64;               // 128
    float* s3    = b3s + 128;
    float* be3s  = s3 + 128;
    float* loc   = be3s + 128;              // [3][128]
    float* centv = loc + 384;               // [4][3]
    int*   outb  = (int*)(centv + 16);      // [4][128]

    const int tid = threadIdx.x;
    const int bId = blockIdx.x;
    const int b   = bId >> 8;
    const int m0  = (bId & 255) << 2;
    const float rs = rsqrtf(1.0f + 1e-5f);

    for (int i = tid; i < 64 * 64; i += 128) { int c = i >> 6, o = i & 63;  w2s[i] = w2[o * 64 + c]; }
    for (int i = tid; i < 64 * 128; i += 128){ int c = i >> 7, o = i & 127; w3s[i] = w3[o * 64 + c]; }
    for (int i = tid; i < 192; i += 128)     { int d = i >> 6, o = i & 63;  w1ps[i] = w1[o * 67 + d]; }
    if (tid < 64) {
        s1[tid] = g1[tid] * rs; be1s[tid] = be1[tid];
        b2s[tid] = b2[tid]; s2[tid] = g2[tid] * rs; be2s[tid] = be2[tid];
    }
    if (tid < 128) { b3s[tid] = b3[tid]; s3[tid] = g3[tid] * rs; be3s[tid] = be3[tid]; }
    for (int i = tid; i < 512; i += 128) outb[i] = 0;
    if (tid < 12) centv[tid] = cent[b * 3 * MCENT + (tid % 3) * MCENT + m0 + tid / 3];
    __syncthreads();

    // gather: warp w handles group w (32 rows)
    {
        const int w = tid >> 5, lane = tid & 31;
        const int m = m0 + w;
        const int* ni = g_nidx + (b * MCENT + m) * KNB;
        const float* pb = pts + b * 3 * NPTS;
        float cx = centv[w * 3], cy = centv[w * 3 + 1], cz = centv[w * 3 + 2];
        int nk = ni[lane];
#pragma unroll 4
        for (int k = 0; k < KNB; k++) {
            int n = __shfl_sync(0xffffffffu, nk, k);
            int r = w * 32 + k;
            if (lane == 0) {
                loc[r]       = pb[n] - cx;
                loc[128 + r] = pb[NPTS + n] - cy;
                loc[256 + r] = pb[2 * NPTS + n] - cz;
            }
            float2 v = *(const float2*)(g_pf + (b * NPTS + n) * 64 + lane * 2);
            *(float2*)(bufA + r * 68 + lane * 2) = v;
        }
    }
    __syncthreads();

    // layer 1: y1 = relu((pf + W1p@local) * s1 + be1), in place in bufA
    {
        const int r = tid;
        float lx = loc[r], ly = loc[128 + r], lz = loc[256 + r];
#pragma unroll
        for (int o = 0; o < 64; o += 4) {
            float4 p  = *(float4*)(bufA + r * 68 + o);
            float4 wx = *(const float4*)(w1ps + o);
            float4 wy = *(const float4*)(w1ps + 64 + o);
            float4 wz = *(const float4*)(w1ps + 128 + o);
            float4 sc = *(const float4*)(s1 + o);
            float4 eb = *(const float4*)(be1s + o);
            p.x = fmaf(wz.x, lz, fmaf(wy.x, ly, fmaf(wx.x, lx, p.x)));
            p.y = fmaf(wz.y, lz, fmaf(wy.y, ly, fmaf(wx.y, lx, p.y)));
            p.z = fmaf(wz.z, lz, fmaf(wy.z, ly, fmaf(wx.z, lx, p.z)));
            p.w = fmaf(wz.w, lz, fmaf(wy.w, ly, fmaf(wx.w, lx, p.w)));
            p.x = fmaxf(fmaf(p.x, sc.x, eb.x), 0.f);
            p.y = fmaxf(fmaf(p.y, sc.y, eb.y), 0.f);
            p.z = fmaxf(fmaf(p.z, sc.z, eb.z), 0.f);
            p.w = fmaxf(fmaf(p.w, sc.w, eb.w), 0.f);
            *(float4*)(bufA + r * 68 + o) = p;
        }
    }
    __syncthreads();

    const int rt = tid >> 3, ct = tid & 7;
    const int r0 = rt * 8, o0 = ct * 8;

    // layer 2: bufB = relu((bufA @ W2^T + b2) * s2 + be2)
    {
        float acc[8][8];
        gemm8x8<64>(bufA, w2s, r0, o0, acc);
        float4 bb0 = *(const float4*)(b2s + o0),  bb1 = *(const float4*)(b2s + o0 + 4);
        float4 ss0 = *(const float4*)(s2 + o0),   ss1 = *(const float4*)(s2 + o0 + 4);
        float4 ee0 = *(const float4*)(be2s + o0), ee1 = *(const float4*)(be2s + o0 + 4);
#pragma unroll
        for (int i = 0; i < 8; i++) {
            float4 lo, hi;
            lo.x = fmaxf(fmaf(acc[i][0] + bb0.x, ss0.x, ee0.x), 0.f);
            lo.y = fmaxf(fmaf(acc[i][1] + bb0.y, ss0.y, ee0.y), 0.f);
            lo.z = fmaxf(fmaf(acc[i][2] + bb0.z, ss0.z, ee0.z), 0.f);
            lo.w = fmaxf(fmaf(acc[i][3] + bb0.w, ss0.w, ee0.w), 0.f);
            hi.x = fmaxf(fmaf(acc[i][4] + bb1.x, ss1.x, ee1.x), 0.f);
            hi.y = fmaxf(fmaf(acc[i][5] + bb1.y, ss1.y, ee1.y), 0.f);
            hi.z = fmaxf(fmaf(acc[i][6] + bb1.z, ss1.z, ee1.z), 0.f);
            hi.w = fmaxf(fmaf(acc[i][7] + bb1.w, ss1.w, ee1.w), 0.f);
            *(float4*)(bufB + (r0 + i) * 68 + o0)     = lo;
            *(float4*)(bufB + (r0 + i) * 68 + o0 + 4) = hi;
        }
    }
    __syncthreads();

    // layer 3 (two col passes) + fused maxpool over K into outb
    const int gg = r0 >> 5;
#pragma unroll 1
    for (int p = 0; p < 2; p++) {
        const int q0 = o0 + p * 64;
        float acc[8][8];
        gemm8x8<128>(bufB, w3s, r0, q0, acc);
        float4 bb0 = *(const float4*)(b3s + q0),  bb1 = *(const float4*)(b3s + q0 + 4);
        float4 ss0 = *(const float4*)(s3 + q0),   ss1 = *(const float4*)(s3 + q0 + 4);
        float4 ee0 = *(const float4*)(be3s + q0), ee1 = *(const float4*)(be3s + q0 + 4);
        float cm[8];
#pragma unroll
        for (int j = 0; j < 8; j++) cm[j] = 0.f;
#pragma unroll
        for (int i = 0; i < 8; i++) {
            cm[0] = fmaxf(cm[0], fmaxf(fmaf(acc[i][0] + bb0.x, ss0.x, ee0.x), 0.f));
            cm[1] = fmaxf(cm[1], fmaxf(fmaf(acc[i][1] + bb0.y, ss0.y, ee0.y), 0.f));
            cm[2] = fmaxf(cm[2], fmaxf(fmaf(acc[i][2] + bb0.z, ss0.z, ee0.z), 0.f));
            cm[3] = fmaxf(cm[3], fmaxf(fmaf(acc[i][3] + bb0.w, ss0.w, ee0.w), 0.f));
            cm[4] = fmaxf(cm[4], fmaxf(fmaf(acc[i][4] + bb1.x, ss1.x, ee1.x), 0.f));
            cm[5] = fmaxf(cm[5], fmaxf(fmaf(acc[i][5] + bb1.y, ss1.y, ee1.y), 0.f));
            cm[6] = fmaxf(cm[6], fmaxf(fmaf(acc[i][6] + bb1.z, ss1.z, ee1.z), 0.f));
            cm[7] = fmaxf(cm[7], fmaxf(fmaf(acc[i][7] + bb1.w, ss1.w, ee1.w), 0.f));
        }
#pragma unroll
        for (int j = 0; j < 8; j++)
            atomicMax(&outb[gg * 128 + q0 + j], __float_as_int(cm[j]));
    }
    __syncthreads();

    // write out[b][o][m0..m0+3] as one float4 per thread
    {
        int o = tid;
        float4 v;
        v.x = __int_as_float(outb[0 * 128 + o]);
        v.y = __int_as_float(outb[1 * 128 + o]);
        v.z = __int_as_float(outb[2 * 128 + o]);
        v.w = __int_as_float(outb[3 * 128 + o]);
        *(float4*)(out + (b * 128 + o) * MCENT + m0) = v;
    }
}

// ---------------------------------------------------------------------------
extern "C" void kernel_launch(void* const* d_in, const int* in_sizes, int n_in,
                              void* d_out, int out_size) {
    const float* points   = (const float*)d_in[0];
    const float* features = (const float*)d_in[1];
    const float* w1  = (const float*)d_in[2];
    const float* b1  = (const float*)d_in[3];
    const float* g1  = (const float*)d_in[4];
    const float* be1 = (const float*)d_in[5];
    const float* w2  = (const float*)d_in[6];
    const float* b2  = (const float*)d_in[7];
    const float* g2  = (const float*)d_in[8];
    const float* be2 = (const float*)d_in[9];
    const float* w3  = (const float*)d_in[10];
    const float* b3  = (const float*)d_in[11];
    const float* g3  = (const float*)d_in[12];
    const float* be3 = (const float*)d_in[13];

    float* cent_out = (float*)d_out;                       // [B][3][M]
    float* out      = cent_out + BATCH * 3 * MCENT;        // [B][128][M]

    const int fps_smem = (3 * NPTS + 4) * 4 + 16 * 8;
    const int mlp_smem = 31504 * 4;
    cudaFuncSetAttribute(fps_kernel, cudaFuncAttributeMaxDynamicSharedMemorySize, fps_smem);
    cudaFuncSetAttribute(mlp_kernel, cudaFuncAttributeMaxDynamicSharedMemorySize, mlp_smem);

    fps_kernel<<<BATCH, 512, fps_smem>>>(points, cent_out);
    pf_kernel<<<dim3(NPTS / 128, BATCH), 128>>>(features, w1, b1);
    ballq_kernel<<<(BATCH * MCENT * 32) / 256, 256>>>(points, cent_out);
    mlp_kernel<<<BATCH * (MCENT / 4), 128, mlp_smem>>>(
        points, w1, g1, be1, w2, b2, g2, be2, w3, b3, g3, be3, cent_out, out);
}

// round 4
// speedup vs baseline: 1.3730x; 1.3730x over previous
#include <cuda_runtime.h>
#include <cstdint>

#define BATCH 16
#define NPTS  4096
#define CH    64
#define MCENT 1024
#define KNB   32
#define RAD2  0.04f

// scratch (allocation-free rule: __device__ globals)
__device__ float g_pf[BATCH * NPTS * 64];        // 16 MB: W1[:,3:]@feat + b1, [b][n][64]
__device__ int   g_nidx[BATCH * MCENT * KNB];    // 2 MB

// packed f32x2 helpers (sm_100+)
#define PK2(out, lo, hi)  asm("mov.b64 %0, {%1, %2};" : "=l"(out) : "f"(lo), "f"(hi))
#define UPK2(lo, hi, in)  asm("mov.b64 {%0, %1}, %2;" : "=f"(lo), "=f"(hi) : "l"(in))
#define ADD2(o, a, b)     asm("add.rn.f32x2 %0, %1, %2;" : "=l"(o) : "l"(a), "l"(b))
#define MUL2(o, a, b)     asm("mul.rn.f32x2 %0, %1, %2;" : "=l"(o) : "l"(a), "l"(b))
#define FMA2(o, a, b, c)  asm("fma.rn.f32x2 %0, %1, %2, %3;" : "=l"(o) : "l"(a), "l"(b), "l"(c))

// ---------------------------------------------------------------------------
// Kernel 1: farthest point sampling. 1 block per batch, 512 threads, 8 pts/thr.
// Packed f32x2 distance update; REDUX-based argmax; single barrier/iteration
// via double-buffered per-warp keys (all warps redo the 16-key final reduce).
// ---------------------------------------------------------------------------
__global__ void __launch_bounds__(512) fps_kernel(const float* __restrict__ pts,
                                                  float* __restrict__ cent_out) {
    extern __shared__ float fs[];
    float* spx = fs;
    float* spy = fs + NPTS;
    float* spz = fs + 2 * NPTS;
    unsigned* swd = (unsigned*)(fs + 3 * NPTS);          // [2][16]
    unsigned* swn = swd + 32;                            // [2][16]

    const int b    = blockIdx.x;
    const int tid  = threadIdx.x;
    const int lane = tid & 31;
    const int warp = tid >> 5;
    const float* pb = pts + b * 3 * NPTS;

    float xs[8], ys[8], zs[8], dist[8];
#pragma unroll
    for (int i = 0; i < 8; i++) {
        int n = tid + i * 512;
        xs[i] = pb[n]; ys[i] = pb[NPTS + n]; zs[i] = pb[2 * NPTS + n];
        spx[n] = xs[i]; spy[n] = ys[i]; spz[n] = zs[i];
        dist[i] = 1e10f;
    }
    unsigned long long X[4], Y[4], Z[4];
#pragma unroll
    for (int j = 0; j < 4; j++) {
        PK2(X[j], xs[2 * j], xs[2 * j + 1]);
        PK2(Y[j], ys[2 * j], ys[2 * j + 1]);
        PK2(Z[j], zs[2 * j], zs[2 * j + 1]);
    }
    __syncthreads();

    float cx = spx[0], cy = spy[0], cz = spz[0];
    float* centb = cent_out + b * 3 * MCENT;
    if (tid == 0) { centb[0] = cx; centb[MCENT] = cy; centb[2 * MCENT] = cz; }

    int p = 0;
    for (int m = 1; m < MCENT; m++) {
        float ncx = -cx, ncy = -cy, ncz = -cz;
        unsigned long long ncx2, ncy2, ncz2;
        PK2(ncx2, ncx, ncx); PK2(ncy2, ncy, ncy); PK2(ncz2, ncz, ncz);
#pragma unroll
        for (int j = 0; j < 4; j++) {
            unsigned long long dx, dy, dz, t;
            ADD2(dx, X[j], ncx2);
            MUL2(t, dx, dx);
            ADD2(dy, Y[j], ncy2);
            FMA2(t, dy, dy, t);
            ADD2(dz, Z[j], ncz2);
            FMA2(t, dz, dz, t);
            float lo, hi; UPK2(lo, hi, t);
            dist[2 * j]     = fminf(dist[2 * j], lo);
            dist[2 * j + 1] = fminf(dist[2 * j + 1], hi);
        }
        // per-thread argmax (ascending local index; strict > keeps earliest)
        float bd = dist[0]; int bi = 0;
#pragma unroll
        for (int i = 1; i < 8; i++) if (dist[i] > bd) { bd = dist[i]; bi = i; }
        unsigned bn = (unsigned)(tid + bi * 512);
        // warp reduce: max dist-bits, then min index among exact ties
        unsigned du = __float_as_uint(bd);
        unsigned wm = __reduce_max_sync(0xffffffffu, du);
        unsigned cd = (du == wm) ? bn : 0xffffffffu;
        unsigned wi = __reduce_min_sync(0xffffffffu, cd);
        if (lane == 0) { swd[p * 16 + warp] = wm; swn[p * 16 + warp] = wi; }
        __syncthreads();
        // every warp reduces the 16 per-warp keys (no 2nd barrier needed)
        unsigned kd = (lane < 16) ? swd[p * 16 + lane] : 0u;
        unsigned kn = (lane < 16) ? swn[p * 16 + lane] : 0xffffffffu;
        unsigned gm = __reduce_max_sync(0xffffffffu, kd);
        unsigned c2 = (kd == gm) ? kn : 0xffffffffu;
        unsigned n  = __reduce_min_sync(0xffffffffu, c2);
        cx = spx[n]; cy = spy[n]; cz = spz[n];
        if (tid == 0) { centb[m] = cx; centb[MCENT + m] = cy; centb[2 * MCENT + m] = cz; }
        p ^= 1;
    }
}

// ---------------------------------------------------------------------------
// Kernel 2: ball query. One warp per centroid; ordered ballot scan over N,
// taking the first K (by index) points with d2 <= R^2, padded with first hit.
// ---------------------------------------------------------------------------
__global__ void __launch_bounds__(256) ballq_kernel(const float* __restrict__ pts,
                                                    const float* __restrict__ cent) {
    int gwarp = (blockIdx.x * blockDim.x + threadIdx.x) >> 5;
    int lane  = threadIdx.x & 31;
    if (gwarp >= BATCH * MCENT) return;
    int b = gwarp >> 10, m = gwarp & 1023;
    const float* pb = pts + b * 3 * NPTS;
    const float* cb = cent + b * 3 * MCENT;
    float cx = cb[m], cy = cb[MCENT + m], cz = cb[2 * MCENT + m];
    float c2 = cx * cx + cy * cy + cz * cz;
    int* ni = g_nidx + (b * MCENT + m) * KNB;

    int cnt = 0, first = -1;
    for (int base = 0; base < NPTS; base += 32) {
        int n = base + lane;
        float x = pb[n], y = pb[NPTS + n], z = pb[2 * NPTS + n];
        float p2  = x * x + y * y + z * z;
        float dot = cx * x + cy * y + cz * z;
        float d2  = c2 + p2 - 2.f * dot;
        bool hit = (d2 <= RAD2);
        unsigned mask = __ballot_sync(0xffffffffu, hit);
        if (mask) {
            if (first < 0) first = base + __ffs(mask) - 1;
            if (hit) {
                int rank = cnt + __popc(mask & ((1u << lane) - 1u));
                if (rank < KNB) ni[rank] = n;
            }
            cnt += __popc(mask);
            if (cnt >= KNB) break;
        }
    }
    if (cnt < KNB) {
        int f = (first < 0) ? (NPTS - 1) : first;
        for (int s = cnt + lane; s < KNB; s += 32) ni[s] = f;
    }
}

// ---------------------------------------------------------------------------
// Kernel 3: precompute pf[b][n][o] = b1[o] + sum_c w1[o][3+c] * feats[b][c][n]
// ---------------------------------------------------------------------------
__global__ void __launch_bounds__(128) pf_kernel(const float* __restrict__ feats,
                                                 const float* __restrict__ w1,
                                                 const float* __restrict__ b1) {
    __shared__ float w1s[64][64];   // [c][o]
    __shared__ float b1s[64];
    int tid = threadIdx.x;
    for (int i = tid; i < 64 * 64; i += 128) {
        int c = i >> 6, o = i & 63;
        w1s[c][o] = w1[o * 67 + 3 + c];
    }
    if (tid < 64) b1s[tid] = b1[tid];
    __syncthreads();

    int b = blockIdx.y;
    int n = blockIdx.x * 128 + tid;
    const float* fb = feats + b * CH * NPTS + n;

    float acc[64];
#pragma unroll
    for (int o = 0; o < 64; o++) acc[o] = b1s[o];
#pragma unroll 4
    for (int c = 0; c < 64; c++) {
        float f = fb[c * NPTS];
#pragma unroll
        for (int o = 0; o < 64; o += 4) {
            float4 w = *(const float4*)&w1s[c][o];
            acc[o]     = fmaf(w.x, f, acc[o]);
            acc[o + 1] = fmaf(w.y, f, acc[o + 1]);
            acc[o + 2] = fmaf(w.z, f, acc[o + 2]);
            acc[o + 3] = fmaf(w.w, f, acc[o + 3]);
        }
    }
    float* dst = g_pf + (b * NPTS + n) * 64;
#pragma unroll
    for (int o = 0; o < 64; o += 4)
        *(float4*)(dst + o) = make_float4(acc[o], acc[o + 1], acc[o + 2], acc[o + 3]);
}

// ---------------------------------------------------------------------------
// Kernel 4: fused gather + 3-layer MLP + maxpool. Block = 4 groups (128 rows),
// 128 threads, 8x8 register tiles. Layer 2 runs IN PLACE in bufA (sync,
// store, sync) so smem fits 2 blocks/SM (8 warps/SM).
// ---------------------------------------------------------------------------
template <int WS>
__device__ __forceinline__ void gemm8x8(const float* __restrict__ A,
                                        const float* __restrict__ W,
                                        int r0, int o0, float (&acc)[8][8]) {
#pragma unroll
    for (int i = 0; i < 8; i++)
#pragma unroll
        for (int j = 0; j < 8; j++) acc[i][j] = 0.f;

#pragma unroll 2
    for (int cc = 0; cc < 64; cc += 4) {
        float4 a[8];
#pragma unroll
        for (int i = 0; i < 8; i++) a[i] = *(const float4*)(A + (r0 + i) * 68 + cc);
#pragma unroll
        for (int j = 0; j < 4; j++) {
            float4 blo = *(const float4*)(W + (cc + j) * WS + o0);
            float4 bhi = *(const float4*)(W + (cc + j) * WS + o0 + 4);
#pragma unroll
            for (int i = 0; i < 8; i++) {
                float av = (j == 0) ? a[i].x : (j == 1) ? a[i].y : (j == 2) ? a[i].z : a[i].w;
                acc[i][0] = fmaf(av, blo.x, acc[i][0]);
                acc[i][1] = fmaf(av, blo.y, acc[i][1]);
                acc[i][2] = fmaf(av, blo.z, acc[i][2]);
                acc[i][3] = fmaf(av, blo.w, acc[i][3]);
                acc[i][4] = fmaf(av, bhi.x, acc[i][4]);
                acc[i][5] = fmaf(av, bhi.y, acc[i][5]);
                acc[i][6] = fmaf(av, bhi.z, acc[i][6]);
                acc[i][7] = fmaf(av, bhi.w, acc[i][7]);
            }
        }
    }
}

__global__ void __launch_bounds__(128) mlp_kernel(
    const float* __restrict__ pts,
    const float* __restrict__ w1, const float* __restrict__ g1, const float* __restrict__ be1,
    const float* __restrict__ w2, const float* __restrict__ b2,
    const float* __restrict__ g2, const float* __restrict__ be2,
    const float* __restrict__ w3, const float* __restrict__ b3,
    const float* __restrict__ g3, const float* __restrict__ be3,
    const float* __restrict__ cent, float* __restrict__ out) {
    extern __shared__ float sm[];
    float* bufA  = sm;                      // 128*68 = 8704
    float* w2s   = bufA + 128 * 68;         // [c][o] 64*64
    float* w3s   = w2s + 64 * 64;           // [c][o] 64*128
    float* w1ps  = w3s + 64 * 128;          // [d][o] 3*64
    float* s1    = w1ps + 192;
    float* be1s  = s1 + 64;
    float* b2s   = be1s + 64;
    float* s2    = b2s + 64;
    float* be2s  = s2 + 64;
    float* b3s   = be2s + 64;               // 128
    float* s3    = b3s + 128;
    float* be3s  = s3 + 128;
    float* loc   = be3s + 128;              // [3][128]
    float* centv = loc + 384;               // [4][3] (+pad)
    int*   outb  = (int*)(centv + 16);      // [4][128]

    const int tid = threadIdx.x;
    const int bId = blockIdx.x;
    const int b   = bId >> 8;
    const int m0  = (bId & 255) << 2;
    const float rs = rsqrtf(1.0f + 1e-5f);

    for (int i = tid; i < 64 * 64; i += 128) { int c = i >> 6, o = i & 63;  w2s[i] = w2[o * 64 + c]; }
    for (int i = tid; i < 64 * 128; i += 128){ int c = i >> 7, o = i & 127; w3s[i] = w3[o * 64 + c]; }
    for (int i = tid; i < 192; i += 128)     { int d = i >> 6, o = i & 63;  w1ps[i] = w1[o * 67 + d]; }
    if (tid < 64) {
        s1[tid] = g1[tid] * rs; be1s[tid] = be1[tid];
        b2s[tid] = b2[tid]; s2[tid] = g2[tid] * rs; be2s[tid] = be2[tid];
    }
    if (tid < 128) { b3s[tid] = b3[tid]; s3[tid] = g3[tid] * rs; be3s[tid] = be3[tid]; }
    for (int i = tid; i < 512; i += 128) outb[i] = 0;
    if (tid < 12) centv[tid] = cent[b * 3 * MCENT + (tid % 3) * MCENT + m0 + tid / 3];
    __syncthreads();

    // gather: warp w handles group w (32 rows)
    {
        const int w = tid >> 5, lane = tid & 31;
        const int m = m0 + w;
        const int* ni = g_nidx + (b * MCENT + m) * KNB;
        const float* pb = pts + b * 3 * NPTS;
        float cx = centv[w * 3], cy = centv[w * 3 + 1], cz = centv[w * 3 + 2];
        int nk = ni[lane];
#pragma unroll 4
        for (int k = 0; k < KNB; k++) {
            int n = __shfl_sync(0xffffffffu, nk, k);
            int r = w * 32 + k;
            if (lane == 0) {
                loc[r]       = pb[n] - cx;
                loc[128 + r] = pb[NPTS + n] - cy;
                loc[256 + r] = pb[2 * NPTS + n] - cz;
            }
            float2 v = *(const float2*)(g_pf + (b * NPTS + n) * 64 + lane * 2);
            *(float2*)(bufA + r * 68 + lane * 2) = v;
        }
    }
    __syncthreads();

    // layer 1: y1 = relu((pf + W1p@local) * s1 + be1), in place in bufA
    {
        const int r = tid;
        float lx = loc[r], ly = loc[128 + r], lz = loc[256 + r];
#pragma unroll
        for (int o = 0; o < 64; o += 4) {
            float4 p  = *(float4*)(bufA + r * 68 + o);
            float4 wx = *(const float4*)(w1ps + o);
            float4 wy = *(const float4*)(w1ps + 64 + o);
            float4 wz = *(const float4*)(w1ps + 128 + o);
            float4 sc = *(const float4*)(s1 + o);
            float4 eb = *(const float4*)(be1s + o);
            p.x = fmaf(wz.x, lz, fmaf(wy.x, ly, fmaf(wx.x, lx, p.x)));
            p.y = fmaf(wz.y, lz, fmaf(wy.y, ly, fmaf(wx.y, lx, p.y)));
            p.z = fmaf(wz.z, lz, fmaf(wy.z, ly, fmaf(wx.z, lx, p.z)));
            p.w = fmaf(wz.w, lz, fmaf(wy.w, ly, fmaf(wx.w, lx, p.w)));
            p.x = fmaxf(fmaf(p.x, sc.x, eb.x), 0.f);
            p.y = fmaxf(fmaf(p.y, sc.y, eb.y), 0.f);
            p.z = fmaxf(fmaf(p.z, sc.z, eb.z), 0.f);
            p.w = fmaxf(fmaf(p.w, sc.w, eb.w), 0.f);
            *(float4*)(bufA + r * 68 + o) = p;
        }
    }
    __syncthreads();

    const int rt = tid >> 3, ct = tid & 7;
    const int r0 = rt * 8, o0 = ct * 8;

    // layer 2 IN PLACE: acc = bufA @ W2^T; sync (all reads done); store; sync
    {
        float acc[8][8];
        gemm8x8<64>(bufA, w2s, r0, o0, acc);
        float4 bb0 = *(const float4*)(b2s + o0),  bb1 = *(const float4*)(b2s + o0 + 4);
        float4 ss0 = *(const float4*)(s2 + o0),   ss1 = *(const float4*)(s2 + o0 + 4);
        float4 ee0 = *(const float4*)(be2s + o0), ee1 = *(const float4*)(be2s + o0 + 4);
#pragma unroll
        for (int i = 0; i < 8; i++) {
            acc[i][0] = fmaxf(fmaf(acc[i][0] + bb0.x, ss0.x, ee0.x), 0.f);
            acc[i][1] = fmaxf(fmaf(acc[i][1] + bb0.y, ss0.y, ee0.y), 0.f);
            acc[i][2] = fmaxf(fmaf(acc[i][2] + bb0.z, ss0.z, ee0.z), 0.f);
            acc[i][3] = fmaxf(fmaf(acc[i][3] + bb0.w, ss0.w, ee0.w), 0.f);
            acc[i][4] = fmaxf(fmaf(acc[i][4] + bb1.x, ss1.x, ee1.x), 0.f);
            acc[i][5] = fmaxf(fmaf(acc[i][5] + bb1.y, ss1.y, ee1.y), 0.f);
            acc[i][6] = fmaxf(fmaf(acc[i][6] + bb1.z, ss1.z, ee1.z), 0.f);
            acc[i][7] = fmaxf(fmaf(acc[i][7] + bb1.w, ss1.w, ee1.w), 0.f);
        }
        __syncthreads();   // all gemm reads of bufA complete
#pragma unroll
        for (int i = 0; i < 8; i++) {
            *(float4*)(bufA + (r0 + i) * 68 + o0)     =
                make_float4(acc[i][0], acc[i][1], acc[i][2], acc[i][3]);
            *(float4*)(bufA + (r0 + i) * 68 + o0 + 4) =
                make_float4(acc[i][4], acc[i][5], acc[i][6], acc[i][7]);
        }
    }
    __syncthreads();

    // layer 3 (two col passes) + fused maxpool over K into outb
    const int gg = r0 >> 5;
#pragma unroll 1
    for (int p = 0; p < 2; p++) {
        const int q0 = o0 + p * 64;
        float acc[8][8];
        gemm8x8<128>(bufA, w3s, r0, q0, acc);
        float4 bb0 = *(const float4*)(b3s + q0),  bb1 = *(const float4*)(b3s + q0 + 4);
        float4 ss0 = *(const float4*)(s3 + q0),   ss1 = *(const float4*)(s3 + q0 + 4);
        float4 ee0 = *(const float4*)(be3s + q0), ee1 = *(const float4*)(be3s + q0 + 4);
        float cm[8];
#pragma unroll
        for (int j = 0; j < 8; j++) cm[j] = 0.f;
#pragma unroll
        for (int i = 0; i < 8; i++) {
            cm[0] = fmaxf(cm[0], fmaxf(fmaf(acc[i][0] + bb0.x, ss0.x, ee0.x), 0.f));
            cm[1] = fmaxf(cm[1], fmaxf(fmaf(acc[i][1] + bb0.y, ss0.y, ee0.y), 0.f));
            cm[2] = fmaxf(cm[2], fmaxf(fmaf(acc[i][2] + bb0.z, ss0.z, ee0.z), 0.f));
            cm[3] = fmaxf(cm[3], fmaxf(fmaf(acc[i][3] + bb0.w, ss0.w, ee0.w), 0.f));
            cm[4] = fmaxf(cm[4], fmaxf(fmaf(acc[i][4] + bb1.x, ss1.x, ee1.x), 0.f));
            cm[5] = fmaxf(cm[5], fmaxf(fmaf(acc[i][5] + bb1.y, ss1.y, ee1.y), 0.f));
            cm[6] = fmaxf(cm[6], fmaxf(fmaf(acc[i][6] + bb1.z, ss1.z, ee1.z), 0.f));
            cm[7] = fmaxf(cm[7], fmaxf(fmaf(acc[i][7] + bb1.w, ss1.w, ee1.w), 0.f));
        }
#pragma unroll
        for (int j = 0; j < 8; j++)
            atomicMax(&outb[gg * 128 + q0 + j], __float_as_int(cm[j]));
    }
    __syncthreads();

    // write out[b][o][m0..m0+3] as one float4 per thread
    {
        int o = tid;
        float4 v;
        v.x = __int_as_float(outb[0 * 128 + o]);
        v.y = __int_as_float(outb[1 * 128 + o]);
        v.z = __int_as_float(outb[2 * 128 + o]);
        v.w = __int_as_float(outb[3 * 128 + o]);
        *(float4*)(out + (b * 128 + o) * MCENT + m0) = v;
    }
}

// ---------------------------------------------------------------------------
extern "C" void kernel_launch(void* const* d_in, const int* in_sizes, int n_in,
                              void* d_out, int out_size) {
    const float* points   = (const float*)d_in[0];
    const float* features = (const float*)d_in[1];
    const float* w1  = (const float*)d_in[2];
    const float* b1  = (const float*)d_in[3];
    const float* g1  = (const float*)d_in[4];
    const float* be1 = (const float*)d_in[5];
    const float* w2  = (const float*)d_in[6];
    const float* b2  = (const float*)d_in[7];
    const float* g2  = (const float*)d_in[8];
    const float* be2 = (const float*)d_in[9];
    const float* w3  = (const float*)d_in[10];
    const float* b3  = (const float*)d_in[11];
    const float* g3  = (const float*)d_in[12];
    const float* be3 = (const float*)d_in[13];

    float* cent_out = (float*)d_out;                       // [B][3][M]
    float* out      = cent_out + BATCH * 3 * MCENT;        // [B][128][M]

    const int fps_smem = 3 * NPTS * 4 + 64 * 4;            // pts + 2x[2][16] keys
    const int mlp_smem = 22992 * 4;                        // 91,968 B -> 2 blocks/SM
    cudaFuncSetAttribute(fps_kernel, cudaFuncAttributeMaxDynamicSharedMemorySize, fps_smem);
    cudaFuncSetAttribute(mlp_kernel, cudaFuncAttributeMaxDynamicSharedMemorySize, mlp_smem);

    fps_kernel<<<BATCH, 512, fps_smem>>>(points, cent_out);
    pf_kernel<<<dim3(NPTS / 128, BATCH), 128>>>(features, w1, b1);
    ballq_kernel<<<(BATCH * MCENT * 32) / 256, 256>>>(points, cent_out);
    mlp_kernel<<<BATCH * (MCENT / 4), 128, mlp_smem>>>(
        points, w1, g1, be1, w2, b2, g2, be2, w3, b3, g3, be3, cent_out, out);
}

// round 7
// speedup vs baseline: 1.5565x; 1.1337x over previous
#include <cuda_runtime.h>
#include <cstdint>

#define BATCH 16
#define NPTS  4096
#define CH    64
#define MCENT 1024
#define KNB   32
#define RAD2  0.04f

typedef unsigned long long u64;

// scratch (allocation-free rule: __device__ globals)
__device__ float g_pf[BATCH * NPTS * 64];        // 16 MB: W1[:,3:]@feat + b1, [b][n][64]
__device__ int   g_nidx[BATCH * MCENT * KNB];    // 2 MB

// packed f32x2 helpers (sm_100+)
#define PK2(out, lo, hi)  asm("mov.b64 %0, {%1, %2};" : "=l"(out) : "f"(lo), "f"(hi))
#define UPK2(lo, hi, in)  asm("mov.b64 {%0, %1}, %2;" : "=f"(lo), "=f"(hi) : "l"(in))
#define ADD2(o, a, b)     asm("add.rn.f32x2 %0, %1, %2;" : "=l"(o) : "l"(a), "l"(b))
#define MUL2(o, a, b)     asm("mul.rn.f32x2 %0, %1, %2;" : "=l"(o) : "l"(a), "l"(b))
#define FMA2(o, a, b, c)  asm("fma.rn.f32x2 %0, %1, %2, %3;" : "=l"(o) : "l"(a), "l"(b), "l"(c))

// bufA addressing: stride 68 floats/row + XOR swizzle of float4 index by (r>>3)&3
// decomposition: r*68 + group(c4>>2)*16 + ((low2(c4) ^ (r>>3)) & 3)*4
__device__ __forceinline__ int aidx(int r, int c4) {
    return r * 68 + (((c4 ^ (r >> 3)) & 3) << 2) + ((c4 >> 2) << 4);
}

// ---------------------------------------------------------------------------
// Kernel 1 (fused): blocks 0..15 do FPS (1 block per batch, 512 thr, 8 pts/thr);
// blocks 16..143 do the pf precompute (hidden under FPS's long tail).
// ---------------------------------------------------------------------------
__global__ void __launch_bounds__(512) fps_pf_kernel(const float* __restrict__ pts,
                                                     const float* __restrict__ feats,
                                                     const float* __restrict__ w1,
                                                     const float* __restrict__ b1,
                                                     float* __restrict__ cent_out) {
    if (blockIdx.x < BATCH) {
        // ----------------- FPS -----------------
        extern __shared__ float fs[];
        float* spx = fs;
        float* spy = fs + NPTS;
        float* spz = fs + 2 * NPTS;
        unsigned* swd = (unsigned*)(fs + 3 * NPTS);          // [2][16]
        unsigned* swn = swd + 32;                            // [2][16]

        const int b    = blockIdx.x;
        const int tid  = threadIdx.x;
        const int lane = tid & 31;
        const int warp = tid >> 5;
        const float* pb = pts + b * 3 * NPTS;

        float xs[8], ys[8], zs[8], dist[8];
#pragma unroll
        for (int i = 0; i < 8; i++) {
            int n = tid + i * 512;
            xs[i] = pb[n]; ys[i] = pb[NPTS + n]; zs[i] = pb[2 * NPTS + n];
            spx[n] = xs[i]; spy[n] = ys[i]; spz[n] = zs[i];
            dist[i] = 1e10f;
        }
        u64 X[4], Y[4], Z[4];
#pragma unroll
        for (int j = 0; j < 4; j++) {
            PK2(X[j], xs[2 * j], xs[2 * j + 1]);
            PK2(Y[j], ys[2 * j], ys[2 * j + 1]);
            PK2(Z[j], zs[2 * j], zs[2 * j + 1]);
        }
        __syncthreads();

        float cx = spx[0], cy = spy[0], cz = spz[0];
        float* centb = cent_out + b * 3 * MCENT;
        if (tid == 0) { centb[0] = cx; centb[MCENT] = cy; centb[2 * MCENT] = cz; }

        int p = 0;
        for (int m = 1; m < MCENT; m++) {
            float ncx = -cx, ncy = -cy, ncz = -cz;
            u64 ncx2, ncy2, ncz2;
            PK2(ncx2, ncx, ncx); PK2(ncy2, ncy, ncy); PK2(ncz2, ncz, ncz);
#pragma unroll
            for (int j = 0; j < 4; j++) {
                u64 dx, dy, dz, t;
                ADD2(dx, X[j], ncx2);
                MUL2(t, dx, dx);
                ADD2(dy, Y[j], ncy2);
                FMA2(t, dy, dy, t);
                ADD2(dz, Z[j], ncz2);
                FMA2(t, dz, dz, t);
                float lo, hi; UPK2(lo, hi, t);
                dist[2 * j]     = fminf(dist[2 * j], lo);
                dist[2 * j + 1] = fminf(dist[2 * j + 1], hi);
            }
            float bd = dist[0]; int bi = 0;
#pragma unroll
            for (int i = 1; i < 8; i++) if (dist[i] > bd) { bd = dist[i]; bi = i; }
            unsigned bn = (unsigned)(tid + bi * 512);
            unsigned du = __float_as_uint(bd);
            unsigned wm = __reduce_max_sync(0xffffffffu, du);
            unsigned cd = (du == wm) ? bn : 0xffffffffu;
            unsigned wi = __reduce_min_sync(0xffffffffu, cd);
            if (lane == 0) { swd[p * 16 + warp] = wm; swn[p * 16 + warp] = wi; }
            __syncthreads();
            unsigned kd = (lane < 16) ? swd[p * 16 + lane] : 0u;
            unsigned kn = (lane < 16) ? swn[p * 16 + lane] : 0xffffffffu;
            unsigned gm = __reduce_max_sync(0xffffffffu, kd);
            unsigned c2 = (kd == gm) ? kn : 0xffffffffu;
            unsigned n  = __reduce_min_sync(0xffffffffu, c2);
            cx = spx[n]; cy = spy[n]; cz = spz[n];
            if (tid == 0) { centb[m] = cx; centb[MCENT + m] = cy; centb[2 * MCENT + m] = cz; }
            p ^= 1;
        }
    } else {
        // ----------------- pf: pf[b][n][o] = b1[o] + W1[:,3:] @ feats[b][:,n] --
        __shared__ float w1s[64][64];   // [c][o]
        __shared__ float b1s[64];
        const int tid = threadIdx.x;
        for (int i = tid; i < 64 * 64; i += 512) {
            int c = i >> 6, o = i & 63;
            w1s[c][o] = w1[o * 67 + 3 + c];
        }
        if (tid < 64) b1s[tid] = b1[tid];
        __syncthreads();

        int bi = blockIdx.x - BATCH;          // 0..127
        int b  = bi >> 3;
        int n  = (bi & 7) * 512 + tid;
        const float* fb = feats + b * CH * NPTS + n;

        float acc[64];
#pragma unroll
        for (int o = 0; o < 64; o++) acc[o] = b1s[o];
#pragma unroll 4
        for (int c = 0; c < 64; c++) {
            float f = fb[c * NPTS];
#pragma unroll
            for (int o = 0; o < 64; o += 4) {
                float4 w = *(const float4*)&w1s[c][o];
                acc[o]     = fmaf(w.x, f, acc[o]);
                acc[o + 1] = fmaf(w.y, f, acc[o + 1]);
                acc[o + 2] = fmaf(w.z, f, acc[o + 2]);
                acc[o + 3] = fmaf(w.w, f, acc[o + 3]);
            }
        }
        float* dst = g_pf + (b * NPTS + n) * 64;
#pragma unroll
        for (int o = 0; o < 64; o += 4)
            *(float4*)(dst + o) = make_float4(acc[o], acc[o + 1], acc[o + 2], acc[o + 3]);
    }
}

// ---------------------------------------------------------------------------
// Kernel 2: ball query. One warp per centroid; ordered ballot scan over N,
// taking the first K (by index) points with d2 <= R^2, padded with first hit.
// ---------------------------------------------------------------------------
__global__ void __launch_bounds__(256) ballq_kernel(const float* __restrict__ pts,
                                                    const float* __restrict__ cent) {
    int gwarp = (blockIdx.x * blockDim.x + threadIdx.x) >> 5;
    int lane  = threadIdx.x & 31;
    if (gwarp >= BATCH * MCENT) return;
    int b = gwarp >> 10, m = gwarp & 1023;
    const float* pb = pts + b * 3 * NPTS;
    const float* cb = cent + b * 3 * MCENT;
    float cx = cb[m], cy = cb[MCENT + m], cz = cb[2 * MCENT + m];
    float c2 = cx * cx + cy * cy + cz * cz;
    int* ni = g_nidx + (b * MCENT + m) * KNB;

    int cnt = 0, first = -1;
    for (int base = 0; base < NPTS; base += 32) {
        int n = base + lane;
        float x = pb[n], y = pb[NPTS + n], z = pb[2 * NPTS + n];
        float p2  = x * x + y * y + z * z;
        float dot = cx * x + cy * y + cz * z;
        float d2  = c2 + p2 - 2.f * dot;
        bool hit = (d2 <= RAD2);
        unsigned mask = __ballot_sync(0xffffffffu, hit);
        if (mask) {
            if (first < 0) first = base + __ffs(mask) - 1;
            if (hit) {
                int rank = cnt + __popc(mask & ((1u << lane) - 1u));
                if (rank < KNB) ni[rank] = n;
            }
            cnt += __popc(mask);
            if (cnt >= KNB) break;
        }
    }
    if (cnt < KNB) {
        int f = (first < 0) ? (NPTS - 1) : first;
        for (int s = cnt + lane; s < KNB; s += 32) ni[s] = f;
    }
}

// ---------------------------------------------------------------------------
// Packed-f32x2 8x8 register-tile GEMM from swizzled bufA + [c][o] weight smem.
// acc[i][j] holds outputs (row r0+i, cols o0+2j, o0+2j+1) packed in f32x2.
// FIX vs R5: pc4 keeps the 16-float group bits ((c4>>2)<<4); only low 2 bits
// of the float4 index are XOR-swizzled (must match aidx()).
// ---------------------------------------------------------------------------
template <int WS>
__device__ __forceinline__ void gemm8x8p(const float* __restrict__ A,
                                         const float* __restrict__ W,
                                         int r0, int o0, int sw, u64 (&acc)[8][4]) {
#pragma unroll
    for (int i = 0; i < 8; i++)
#pragma unroll
        for (int j = 0; j < 4; j++) acc[i][j] = 0ull;

#pragma unroll 2
    for (int cc = 0; cc < 64; cc += 4) {
        const int c4  = cc >> 2;
        const int pc4 = ((c4 >> 2) << 4) + (((c4 ^ sw) & 3) << 2);  // swizzled float offset
        float4 a[8];
#pragma unroll
        for (int i = 0; i < 8; i++)
            a[i] = *(const float4*)(A + (r0 + i) * 68 + pc4);
#pragma unroll
        for (int j = 0; j < 4; j++) {
            const float* wrow = W + (cc + j) * WS + o0;
            ulonglong2 wA = *(const ulonglong2*)(wrow);
            ulonglong2 wB = *(const ulonglong2*)(wrow + 4);
#pragma unroll
            for (int i = 0; i < 8; i++) {
                float av = (j == 0) ? a[i].x : (j == 1) ? a[i].y : (j == 2) ? a[i].z : a[i].w;
                u64 ap; PK2(ap, av, av);
                FMA2(acc[i][0], ap, wA.x, acc[i][0]);
                FMA2(acc[i][1], ap, wA.y, acc[i][1]);
                FMA2(acc[i][2], ap, wB.x, acc[i][2]);
                FMA2(acc[i][3], ap, wB.y, acc[i][3]);
            }
        }
    }
}

// ---------------------------------------------------------------------------
// Kernel 3: fused gather + 3-layer MLP + maxpool. Block = 4 groups (128 rows),
// 128 threads. bufA swizzled (conflict-free gemm loads), layer 2 in place.
// ---------------------------------------------------------------------------
__global__ void __launch_bounds__(128) mlp_kernel(
    const float* __restrict__ pts,
    const float* __restrict__ w1, const float* __restrict__ g1, const float* __restrict__ be1,
    const float* __restrict__ w2, const float* __restrict__ b2,
    const float* __restrict__ g2, const float* __restrict__ be2,
    const float* __restrict__ w3, const float* __restrict__ b3,
    const float* __restrict__ g3, const float* __restrict__ be3,
    const float* __restrict__ cent, float* __restrict__ out) {
    extern __shared__ float sm[];
    float* bufA  = sm;                      // 128*68 = 8704 (swizzled)
    float* w2s   = bufA + 128 * 68;         // [c][o] 64*64
    float* w3s   = w2s + 64 * 64;           // [c][o] 64*128
    float* w1ps  = w3s + 64 * 128;          // [d][o] 3*64
    float* s1    = w1ps + 192;
    float* be1s  = s1 + 64;
    float* b2s   = be1s + 64;
    float* s2    = b2s + 64;
    float* be2s  = s2 + 64;
    float* b3s   = be2s + 64;               // 128
    float* s3    = b3s + 128;
    float* be3s  = s3 + 128;
    float* loc   = be3s + 128;              // [3][128]
    float* centv = loc + 384;               // [4][3] (+pad)
    int*   outb  = (int*)(centv + 16);      // [4][128]

    const int tid = threadIdx.x;
    const int bId = blockIdx.x;
    const int b   = bId >> 8;
    const int m0  = (bId & 255) << 2;
    const float rs = rsqrtf(1.0f + 1e-5f);

    for (int i = tid; i < 64 * 64; i += 128) { int c = i >> 6, o = i & 63;  w2s[i] = w2[o * 64 + c]; }
    for (int i = tid; i < 64 * 128; i += 128){ int c = i >> 7, o = i & 127; w3s[i] = w3[o * 64 + c]; }
    for (int i = tid; i < 192; i += 128)     { int d = i >> 6, o = i & 63;  w1ps[i] = w1[o * 67 + d]; }
    if (tid < 64) {
        s1[tid] = g1[tid] * rs; be1s[tid] = be1[tid];
        b2s[tid] = b2[tid]; s2[tid] = g2[tid] * rs; be2s[tid] = be2[tid];
    }
    if (tid < 128) { b3s[tid] = b3[tid]; s3[tid] = g3[tid] * rs; be3s[tid] = be3[tid]; }
    for (int i = tid; i < 512; i += 128) outb[i] = 0;
    if (tid < 12) centv[tid] = cent[b * 3 * MCENT + (tid % 3) * MCENT + m0 + tid / 3];
    __syncthreads();

    // gather: warp w handles group w (32 rows); writes swizzled float2s
    {
        const int w = tid >> 5, lane = tid & 31;
        const int m = m0 + w;
        const int* ni = g_nidx + (b * MCENT + m) * KNB;
        const float* pb = pts + b * 3 * NPTS;
        float cx = centv[w * 3], cy = centv[w * 3 + 1], cz = centv[w * 3 + 2];
        int nk = ni[lane];
#pragma unroll 4
        for (int k = 0; k < KNB; k++) {
            int n = __shfl_sync(0xffffffffu, nk, k);
            int r = w * 32 + k;
            if (lane == 0) {
                loc[r]       = pb[n] - cx;
                loc[128 + r] = pb[NPTS + n] - cy;
                loc[256 + r] = pb[2 * NPTS + n] - cz;
            }
            float2 v = *(const float2*)(g_pf + (b * NPTS + n) * 64 + lane * 2);
            *(float2*)(bufA + aidx(r, lane >> 1) + ((lane & 1) << 1)) = v;
        }
    }
    __syncthreads();

    // layer 1: y1 = relu((pf + W1p@local) * s1 + be1), in place in bufA
    {
        const int r = tid;
        float lx = loc[r], ly = loc[128 + r], lz = loc[256 + r];
#pragma unroll
        for (int o = 0; o < 64; o += 4) {
            float* ap = bufA + aidx(r, o >> 2);
            float4 p  = *(float4*)ap;
            float4 wx = *(const float4*)(w1ps + o);
            float4 wy = *(const float4*)(w1ps + 64 + o);
            float4 wz = *(const float4*)(w1ps + 128 + o);
            float4 sc = *(const float4*)(s1 + o);
            float4 eb = *(const float4*)(be1s + o);
            p.x = fmaf(wz.x, lz, fmaf(wy.x, ly, fmaf(wx.x, lx, p.x)));
            p.y = fmaf(wz.y, lz, fmaf(wy.y, ly, fmaf(wx.y, lx, p.y)));
            p.z = fmaf(wz.z, lz, fmaf(wy.z, ly, fmaf(wx.z, lx, p.z)));
            p.w = fmaf(wz.w, lz, fmaf(wy.w, ly, fmaf(wx.w, lx, p.w)));
            p.x = fmaxf(fmaf(p.x, sc.x, eb.x), 0.f);
            p.y = fmaxf(fmaf(p.y, sc.y, eb.y), 0.f);
            p.z = fmaxf(fmaf(p.z, sc.z, eb.z), 0.f);
            p.w = fmaxf(fmaf(p.w, sc.w, eb.w), 0.f);
            *(float4*)ap = p;
        }
    }
    __syncthreads();

    const int rt = tid >> 3, ct = tid & 7;
    const int r0 = rt * 8, o0 = ct * 8;
    const int sw = rt & 3;

    // layer 2 IN PLACE: packed acc; sync (all reads done); store; sync
    {
        u64 acc[8][4];
        gemm8x8p<64>(bufA, w2s, r0, o0, sw, acc);
        float ac[8][8];
#pragma unroll
        for (int i = 0; i < 8; i++)
#pragma unroll
            for (int j = 0; j < 4; j++) UPK2(ac[i][2 * j], ac[i][2 * j + 1], acc[i][j]);
        float4 bb0 = *(const float4*)(b2s + o0),  bb1 = *(const float4*)(b2s + o0 + 4);
        float4 ss0 = *(const float4*)(s2 + o0),   ss1 = *(const float4*)(s2 + o0 + 4);
        float4 ee0 = *(const float4*)(be2s + o0), ee1 = *(const float4*)(be2s + o0 + 4);
#pragma unroll
        for (int i = 0; i < 8; i++) {
            ac[i][0] = fmaxf(fmaf(ac[i][0] + bb0.x, ss0.x, ee0.x), 0.f);
            ac[i][1] = fmaxf(fmaf(ac[i][1] + bb0.y, ss0.y, ee0.y), 0.f);
            ac[i][2] = fmaxf(fmaf(ac[i][2] + bb0.z, ss0.z, ee0.z), 0.f);
            ac[i][3] = fmaxf(fmaf(ac[i][3] + bb0.w, ss0.w, ee0.w), 0.f);
            ac[i][4] = fmaxf(fmaf(ac[i][4] + bb1.x, ss1.x, ee1.x), 0.f);
            ac[i][5] = fmaxf(fmaf(ac[i][5] + bb1.y, ss1.y, ee1.y), 0.f);
            ac[i][6] = fmaxf(fmaf(ac[i][6] + bb1.z, ss1.z, ee1.z), 0.f);
            ac[i][7] = fmaxf(fmaf(ac[i][7] + bb1.w, ss1.w, ee1.w), 0.f);
        }
        __syncthreads();   // all gemm reads of bufA complete
        const int c4a = o0 >> 2;
#pragma unroll
        for (int i = 0; i < 8; i++) {
            *(float4*)(bufA + aidx(r0 + i, c4a)) =
                make_float4(ac[i][0], ac[i][1], ac[i][2], ac[i][3]);
            *(float4*)(bufA + aidx(r0 + i, c4a + 1)) =
                make_float4(ac[i][4], ac[i][5], ac[i][6], ac[i][7]);
        }
    }
    __syncthreads();

    // layer 3 (two col passes) + fused maxpool over K into outb
    const int gg = r0 >> 5;
#pragma unroll 1
    for (int p = 0; p < 2; p++) {
        const int q0 = o0 + p * 64;
        u64 acc[8][4];
        gemm8x8p<128>(bufA, w3s, r0, q0, sw, acc);
        float ac[8][8];
#pragma unroll
        for (int i = 0; i < 8; i++)
#pragma unroll
            for (int j = 0; j < 4; j++) UPK2(ac[i][2 * j], ac[i][2 * j + 1], acc[i][j]);
        float4 bb0 = *(const float4*)(b3s + q0),  bb1 = *(const float4*)(b3s + q0 + 4);
        float4 ss0 = *(const float4*)(s3 + q0),   ss1 = *(const float4*)(s3 + q0 + 4);
        float4 ee0 = *(const float4*)(be3s + q0), ee1 = *(const float4*)(be3s + q0 + 4);
        float cm[8];
#pragma unroll
        for (int j = 0; j < 8; j++) cm[j] = 0.f;
#pragma unroll
        for (int i = 0; i < 8; i++) {
            cm[0] = fmaxf(cm[0], fmaxf(fmaf(ac[i][0] + bb0.x, ss0.x, ee0.x), 0.f));
            cm[1] = fmaxf(cm[1], fmaxf(fmaf(ac[i][1] + bb0.y, ss0.y, ee0.y), 0.f));
            cm[2] = fmaxf(cm[2], fmaxf(fmaf(ac[i][2] + bb0.z, ss0.z, ee0.z), 0.f));
            cm[3] = fmaxf(cm[3], fmaxf(fmaf(ac[i][3] + bb0.w, ss0.w, ee0.w), 0.f));
            cm[4] = fmaxf(cm[4], fmaxf(fmaf(ac[i][4] + bb1.x, ss1.x, ee1.x), 0.f));
            cm[5] = fmaxf(cm[5], fmaxf(fmaf(ac[i][5] + bb1.y, ss1.y, ee1.y), 0.f));
            cm[6] = fmaxf(cm[6], fmaxf(fmaf(ac[i][6] + bb1.z, ss1.z, ee1.z), 0.f));
            cm[7] = fmaxf(cm[7], fmaxf(fmaf(ac[i][7] + bb1.w, ss1.w, ee1.w), 0.f));
        }
#pragma unroll
        for (int j = 0; j < 8; j++)
            atomicMax(&outb[gg * 128 + q0 + j], __float_as_int(cm[j]));
    }
    __syncthreads();

    // write out[b][o][m0..m0+3] as one float4 per thread
    {
        int o = tid;
        float4 v;
        v.x = __int_as_float(outb[0 * 128 + o]);
        v.y = __int_as_float(outb[1 * 128 + o]);
        v.z = __int_as_float(outb[2 * 128 + o]);
        v.w = __int_as_float(outb[3 * 128 + o]);
        *(float4*)(out + (b * 128 + o) * MCENT + m0) = v;
    }
}

// ---------------------------------------------------------------------------
extern "C" void kernel_launch(void* const* d_in, const int* in_sizes, int n_in,
                              void* d_out, int out_size) {
    const float* points   = (const float*)d_in[0];
    const float* features = (const float*)d_in[1];
    const float* w1  = (const float*)d_in[2];
    const float* b1  = (const float*)d_in[3];
    const float* g1  = (const float*)d_in[4];
    const float* be1 = (const float*)d_in[5];
    const float* w2  = (const float*)d_in[6];
    const float* b2  = (const float*)d_in[7];
    const float* g2  = (const float*)d_in[8];
    const float* be2 = (const float*)d_in[9];
    const float* w3  = (const float*)d_in[10];
    const float* b3  = (const float*)d_in[11];
    const float* g3  = (const float*)d_in[12];
    const float* be3 = (const float*)d_in[13];

    float* cent_out = (float*)d_out;                       // [B][3][M]
    float* out      = cent_out + BATCH * 3 * MCENT;        // [B][128][M]

    const int fps_smem = 3 * NPTS * 4 + 64 * 4;            // pts + 2x[2][16] keys
    const int mlp_smem = 22992 * 4;                        // 91,968 B -> 2 blocks/SM
    cudaFuncSetAttribute(fps_pf_kernel, cudaFuncAttributeMaxDynamicSharedMemorySize, fps_smem);
    cudaFuncSetAttribute(mlp_kernel, cudaFuncAttributeMaxDynamicSharedMemorySize, mlp_smem);

    fps_pf_kernel<<<BATCH + BATCH * 8, 512, fps_smem>>>(points, features, w1, b1, cent_out);
    ballq_kernel<<<(BATCH * MCENT * 32) / 256, 256>>>(points, cent_out);
    mlp_kernel<<<BATCH * (MCENT / 4), 128, mlp_smem>>>(
        points, w1, g1, be1, w2, b2, g2, be2, w3, b3, g3, be3, cent_out, out);
}